// round 2
// baseline (speedup 1.0000x reference)
#include <cuda_runtime.h>
#include <cuda_bf16.h>

// Problem constants
#define Bn   8
#define Cn   64
#define Nn   2048
#define Mm   32
#define EMB  256
#define MFREQ 4032
#define Pn   2048            // 2*m*m used modes

// Scratch (device globals; no allocation allowed)
__device__ float g_y_re[Bn * Cn * Pn];       // [b][c][p]
__device__ float g_y_im[Bn * Cn * Pn];
__device__ float g_phi_re[Bn * 64 * 32];     // [b][x][y]
__device__ float g_phi_im[Bn * 64 * 32];
__device__ float g_xf_re[Bn * MFREQ * Cn];   // [b][k][c]
__device__ float g_xf_im[Bn * MFREQ * Cn];

// ---------------------------------------------------------------------------
// Packed dual-fp32 helpers (Blackwell FFMA2 via PTX fma.rn.f32x2)
// ---------------------------------------------------------------------------
typedef unsigned long long u64;

__device__ __forceinline__ u64 fma2(u64 a, u64 b, u64 c) {
    u64 d;
    asm("fma.rn.f32x2 %0, %1, %2, %3;" : "=l"(d) : "l"(a), "l"(b), "l"(c));
    return d;
}
__device__ __forceinline__ u64 dup2(float a) {
    u64 d;
    asm("mov.b64 %0, {%1, %1};" : "=l"(d) : "f"(a));
    return d;
}
__device__ __forceinline__ float2 unp2(u64 v) {
    float lo, hi;
    asm("mov.b64 {%0, %1}, %2;" : "=f"(lo), "=f"(hi) : "l"(v));
    return make_float2(lo, hi);
}

// ---------------------------------------------------------------------------
// Stage B: phi[b][x][y] = sum_e m[x<32?1:2][xl][y][e] * emb[b][e]  (re & im)
// grid (64, 8) = (x, b); 256 threads = 8 warps; each warp does 8 reductions.
// ---------------------------------------------------------------------------
__global__ void __launch_bounds__(256) phi_kernel(
    const float* __restrict__ emb,
    const float* __restrict__ m1r, const float* __restrict__ m1i,
    const float* __restrict__ m2r, const float* __restrict__ m2i)
{
    int x = blockIdx.x, b = blockIdx.y;
    __shared__ float es[EMB];
    int t = threadIdx.x;
    es[t] = emb[b * EMB + t];
    __syncthreads();

    int w = t >> 5, lane = t & 31;
    int xl = x & 31;
    const float* mr = (x < 32) ? m1r : m2r;
    const float* mi = (x < 32) ? m1i : m2i;

    #pragma unroll
    for (int task = 0; task < 8; task++) {
        int tid = w * 8 + task;           // 0..63: <32 -> re, >=32 -> im
        int y = tid & 31;
        const float* src = ((tid < 32) ? mr : mi) + (xl * 32 + y) * EMB;
        float s = 0.f;
        #pragma unroll
        for (int q = 0; q < 8; q++) {
            int e = lane + q * 32;
            s += src[e] * es[e];
        }
        #pragma unroll
        for (int off = 16; off; off >>= 1)
            s += __shfl_down_sync(0xffffffffu, s, off);
        if (lane == 0) {
            float* dst = (tid < 32) ? g_phi_re : g_phi_im;
            dst[(b * 64 + x) * 32 + y] = s;
        }
    }
}

// ---------------------------------------------------------------------------
// Stage A: forward NUFT restricted to used modes, packed complex FFMA2.
// y[b][c][p] = sum_n Vf[f(p)][n] * x[b][c][n]   (f(p) = (p/32)*63 + p%32)
// grid (32, 8) = (p-tile, b); 256 threads; 64c x 64p tile; K-tiles of 32.
// smem B-operand holds {re,im} interleaved; acc[i][j] = packed {y_re, y_im}.
// ---------------------------------------------------------------------------
__global__ void __launch_bounds__(256) fwd_gemm(
    const float* __restrict__ x,
    const float* __restrict__ Vfr, const float* __restrict__ Vfi)
{
    int p0 = blockIdx.x * 64;
    int b  = blockIdx.y;

    __shared__ float xs[32][68];    // [n_local][c]
    __shared__ float vb[32][132];   // [n_local][{re,im} x 64 p_local]

    int t = threadIdx.x;
    int tx = t & 15, ty = t >> 4;

    u64 acc[4][4];                  // [i=c][j=p] packed {re, im}
    #pragma unroll
    for (int i = 0; i < 4; i++)
        #pragma unroll
        for (int j = 0; j < 4; j++) acc[i][j] = 0ULL;

    const float* xb = x + (size_t)b * Cn * Nn;
    int nl = t & 31, r0 = t >> 5;

    for (int k0 = 0; k0 < Nn; k0 += 32) {
        #pragma unroll
        for (int it = 0; it < 8; it++) {
            int c = r0 + it * 8;
            xs[nl][c] = xb[c * Nn + k0 + nl];
        }
        #pragma unroll
        for (int it = 0; it < 8; it++) {
            int pl = r0 + it * 8;
            int p  = p0 + pl;
            int f  = (p >> 5) * 63 + (p & 31);
            size_t src = (size_t)f * Nn + k0 + nl;
            *(float2*)&vb[nl][2 * pl] = make_float2(Vfr[src], Vfi[src]);
        }
        __syncthreads();

        #pragma unroll
        for (int k = 0; k < 32; k++) {
            float4 a = *(const float4*)&xs[k][ty * 4];
            u64 a2[4] = {dup2(a.x), dup2(a.y), dup2(a.z), dup2(a.w)};
            const u64* bp = (const u64*)&vb[k][tx * 8];
            u64 b0 = bp[0], b1 = bp[1], b2 = bp[2], b3 = bp[3];
            #pragma unroll
            for (int i = 0; i < 4; i++) {
                acc[i][0] = fma2(a2[i], b0, acc[i][0]);
                acc[i][1] = fma2(a2[i], b1, acc[i][1]);
                acc[i][2] = fma2(a2[i], b2, acc[i][2]);
                acc[i][3] = fma2(a2[i], b3, acc[i][3]);
            }
        }
        __syncthreads();
    }

    #pragma unroll
    for (int i = 0; i < 4; i++) {
        int c = ty * 4 + i;
        size_t base = ((size_t)b * Cn + c) * Pn + p0 + tx * 4;
        float2 v0 = unp2(acc[i][0]), v1 = unp2(acc[i][1]);
        float2 v2 = unp2(acc[i][2]), v3 = unp2(acc[i][3]);
        *(float4*)&g_y_re[base] = make_float4(v0.x, v1.x, v2.x, v3.x);
        *(float4*)&g_y_im[base] = make_float4(v0.y, v1.y, v2.y, v3.y);
    }
}

// ---------------------------------------------------------------------------
// Stage C+D: per-mode channel mix (complex), phi modulation, Hermitian write.
// grid (64, 8) = (x, b); 256 threads; thread handles y = t&31, o in [o_base, o_base+8)
// ---------------------------------------------------------------------------
__global__ void __launch_bounds__(256) mode_mix(
    const float* __restrict__ w1r, const float* __restrict__ w1i,
    const float* __restrict__ w2r, const float* __restrict__ w2i)
{
    int x = blockIdx.x, b = blockIdx.y;
    int t = threadIdx.x;
    int y = t & 31;
    int o_base = (t >> 5) * 8;
    int xl = x & 31;
    int p  = x * 32 + y;

    const float* wr = (x < 32) ? w1r : w2r;
    const float* wi = (x < 32) ? w1i : w2i;

    float sR[8] = {}, sI[8] = {};

    for (int i = 0; i < Cn; i++) {
        size_t yb = ((size_t)b * Cn + i) * Pn + p;
        float inR = g_y_re[yb];
        float inI = g_y_im[yb];
        size_t wbase = (((size_t)i * 64 + o_base) * 32 + xl) * 32 + y;
        #pragma unroll
        for (int j = 0; j < 8; j++) {
            float wre = __ldg(&wr[wbase + (size_t)j * 1024]);
            float wim = __ldg(&wi[wbase + (size_t)j * 1024]);
            sR[j] += wre * inR - wim * inI;
            sI[j] += wre * inI + wim * inR;
        }
    }

    float phr = g_phi_re[(b * 64 + x) * 32 + y];
    float phm = g_phi_im[(b * 64 + x) * 32 + y];

    #pragma unroll
    for (int j = 0; j < 8; j++) {
        int o = o_base + j;
        float oR = phr * sR[j] - phm * sI[j];
        float oI = phr * sI[j] + phm * sR[j];
        size_t d1 = ((size_t)b * MFREQ + p) * Cn + o;
        g_xf_re[d1] = oR;
        g_xf_im[d1] = oI;
        if (p >= 64) {  // uniform per block (x >= 2)
            int k2 = 4095 - p;
            size_t d2 = ((size_t)b * MFREQ + k2) * Cn + (63 - o);
            g_xf_re[d2] = oR;
            g_xf_im[d2] = -oI;
        }
    }
}

// ---------------------------------------------------------------------------
// Stage E: inverse NUFT, real part, packed complex FFMA2.
// out[b][c][n] = (2/N) * sum_k ( Vi_re[n][k]*xf_re[b][k][c] - Vi_im[n][k]*xf_im[b][k][c] )
// smem: av = {Vi_re, Vi_im} interleaved; xv = {xf_re, -xf_im} interleaved.
// acc[i][j] = packed { sum re*re , sum (-im)*im } -> output = lo + hi.
// grid (32, 8) = (n-tile, b); 256 threads; 64c x 64n tile; K = 4032 in tiles of 32.
// ---------------------------------------------------------------------------
__global__ void __launch_bounds__(256) inv_gemm(
    const float* __restrict__ Vir, const float* __restrict__ Vii,
    float* __restrict__ out)
{
    int n0 = blockIdx.x * 64;
    int b  = blockIdx.y;

    __shared__ float av[32][132];   // [k_local][{re,im} x 64 n_local]
    __shared__ float xv[32][132];   // [k_local][{re,-im} x 64 c]

    int t = threadIdx.x;
    int tx = t & 15, ty = t >> 4;

    u64 acc[4][4];                  // [i=c][j=n]
    #pragma unroll
    for (int i = 0; i < 4; i++)
        #pragma unroll
        for (int j = 0; j < 4; j++) acc[i][j] = 0ULL;

    int kl = t & 31, r0 = t >> 5;
    int cc = t & 63, kr0 = t >> 6;   // 0..3

    for (int k0 = 0; k0 < MFREQ; k0 += 32) {
        #pragma unroll
        for (int it = 0; it < 8; it++) {
            int nr = r0 + it * 8;
            size_t src = (size_t)(n0 + nr) * MFREQ + k0 + kl;
            *(float2*)&av[kl][2 * nr] = make_float2(Vir[src], Vii[src]);
        }
        #pragma unroll
        for (int it = 0; it < 8; it++) {
            int kr = kr0 + it * 4;
            size_t src = ((size_t)b * MFREQ + k0 + kr) * Cn + cc;
            *(float2*)&xv[kr][2 * cc] = make_float2(g_xf_re[src], -g_xf_im[src]);
        }
        __syncthreads();

        #pragma unroll
        for (int k = 0; k < 32; k++) {
            const u64* cp = (const u64*)&xv[k][ty * 8];
            const u64* np = (const u64*)&av[k][tx * 8];
            u64 c0 = cp[0], c1 = cp[1], c2 = cp[2], c3 = cp[3];
            u64 m0 = np[0], m1 = np[1], m2 = np[2], m3 = np[3];
            acc[0][0] = fma2(c0, m0, acc[0][0]);
            acc[0][1] = fma2(c0, m1, acc[0][1]);
            acc[0][2] = fma2(c0, m2, acc[0][2]);
            acc[0][3] = fma2(c0, m3, acc[0][3]);
            acc[1][0] = fma2(c1, m0, acc[1][0]);
            acc[1][1] = fma2(c1, m1, acc[1][1]);
            acc[1][2] = fma2(c1, m2, acc[1][2]);
            acc[1][3] = fma2(c1, m3, acc[1][3]);
            acc[2][0] = fma2(c2, m0, acc[2][0]);
            acc[2][1] = fma2(c2, m1, acc[2][1]);
            acc[2][2] = fma2(c2, m2, acc[2][2]);
            acc[2][3] = fma2(c2, m3, acc[2][3]);
            acc[3][0] = fma2(c3, m0, acc[3][0]);
            acc[3][1] = fma2(c3, m1, acc[3][1]);
            acc[3][2] = fma2(c3, m2, acc[3][2]);
            acc[3][3] = fma2(c3, m3, acc[3][3]);
        }
        __syncthreads();
    }

    const float s = 2.0f / (float)Nn;
    #pragma unroll
    for (int i = 0; i < 4; i++) {
        int c = ty * 4 + i;
        size_t dst = ((size_t)b * Cn + c) * Nn + n0 + tx * 4;
        float2 v0 = unp2(acc[i][0]), v1 = unp2(acc[i][1]);
        float2 v2 = unp2(acc[i][2]), v3 = unp2(acc[i][3]);
        *(float4*)&out[dst] = make_float4((v0.x + v0.y) * s, (v1.x + v1.y) * s,
                                          (v2.x + v2.y) * s, (v3.x + v3.y) * s);
    }
}

// ---------------------------------------------------------------------------
extern "C" void kernel_launch(void* const* d_in, const int* in_sizes, int n_in,
                              void* d_out, int out_size)
{
    const float* x    = (const float*)d_in[0];
    const float* emb  = (const float*)d_in[1];
    const float* Vfr  = (const float*)d_in[2];
    const float* Vfi  = (const float*)d_in[3];
    const float* Vir  = (const float*)d_in[4];
    const float* Vii  = (const float*)d_in[5];
    const float* w1r  = (const float*)d_in[6];
    const float* w1i  = (const float*)d_in[7];
    const float* w2r  = (const float*)d_in[8];
    const float* w2i  = (const float*)d_in[9];
    const float* m1r  = (const float*)d_in[10];
    const float* m1i  = (const float*)d_in[11];
    const float* m2r  = (const float*)d_in[12];
    const float* m2i  = (const float*)d_in[13];
    float* out = (float*)d_out;

    phi_kernel<<<dim3(64, 8), 256>>>(emb, m1r, m1i, m2r, m2i);
    fwd_gemm  <<<dim3(32, 8), 256>>>(x, Vfr, Vfi);
    mode_mix  <<<dim3(64, 8), 256>>>(w1r, w1i, w2r, w2i);
    inv_gemm  <<<dim3(32, 8), 256>>>(Vir, Vii, out);
}

// round 3
// speedup vs baseline: 1.0565x; 1.0565x over previous
#include <cuda_runtime.h>
#include <cuda_bf16.h>

// Problem constants
#define Bn   8
#define Cn   64
#define Nn   2048
#define Mm   32
#define EMB  256
#define MFREQ 4032
#define Pn   2048            // 2*m*m used modes

#define BCP  (Bn * Cn * Pn)  // 1,048,576
#define BCN  (Bn * Cn * Nn)  // 1,048,576

// Scratch (device globals; no allocation allowed)
__device__ float g_yp_re[2 * BCP];           // fwd split-K partials [s][b][c][p]
__device__ float g_yp_im[2 * BCP];
__device__ float g_phi_re[Bn * 64 * 32];     // [b][x][y]
__device__ float g_phi_im[Bn * 64 * 32];
__device__ float g_xf_re[Bn * MFREQ * Cn];   // [b][k][c]
__device__ float g_xf_im[Bn * MFREQ * Cn];
__device__ float g_op[4 * BCN];              // inv split-K partials [s][b][c][n]

// ---------------------------------------------------------------------------
// Packed dual-fp32 helpers (Blackwell FFMA2 via PTX fma.rn.f32x2)
// ---------------------------------------------------------------------------
typedef unsigned long long u64;

__device__ __forceinline__ u64 fma2(u64 a, u64 b, u64 c) {
    u64 d;
    asm("fma.rn.f32x2 %0, %1, %2, %3;" : "=l"(d) : "l"(a), "l"(b), "l"(c));
    return d;
}
__device__ __forceinline__ u64 dup2(float a) {
    u64 d;
    asm("mov.b64 %0, {%1, %1};" : "=l"(d) : "f"(a));
    return d;
}
__device__ __forceinline__ float2 unp2(u64 v) {
    float lo, hi;
    asm("mov.b64 {%0, %1}, %2;" : "=f"(lo), "=f"(hi) : "l"(v));
    return make_float2(lo, hi);
}

// ---------------------------------------------------------------------------
// Stage B: phi[b][x][y] = sum_e m[x<32?1:2][xl][y][e] * emb[b][e]  (re & im)
// ---------------------------------------------------------------------------
__global__ void __launch_bounds__(256) phi_kernel(
    const float* __restrict__ emb,
    const float* __restrict__ m1r, const float* __restrict__ m1i,
    const float* __restrict__ m2r, const float* __restrict__ m2i)
{
    int x = blockIdx.x, b = blockIdx.y;
    __shared__ float es[EMB];
    int t = threadIdx.x;
    es[t] = emb[b * EMB + t];
    __syncthreads();

    int w = t >> 5, lane = t & 31;
    int xl = x & 31;
    const float* mr = (x < 32) ? m1r : m2r;
    const float* mi = (x < 32) ? m1i : m2i;

    #pragma unroll
    for (int task = 0; task < 8; task++) {
        int tid = w * 8 + task;           // 0..63: <32 -> re, >=32 -> im
        int y = tid & 31;
        const float* src = ((tid < 32) ? mr : mi) + (xl * 32 + y) * EMB;
        float s = 0.f;
        #pragma unroll
        for (int q = 0; q < 8; q++) {
            int e = lane + q * 32;
            s += src[e] * es[e];
        }
        #pragma unroll
        for (int off = 16; off; off >>= 1)
            s += __shfl_down_sync(0xffffffffu, s, off);
        if (lane == 0) {
            float* dst = (tid < 32) ? g_phi_re : g_phi_im;
            dst[(b * 64 + x) * 32 + y] = s;
        }
    }
}

// ---------------------------------------------------------------------------
// Stage A: forward NUFT restricted to used modes, packed complex FFMA2.
// Split-K = 2: blockIdx.z = s handles n in [s*1024, s*1024+1024).
// grid (32, 8, 2); 256 threads; 64c x 64p tile; K-tiles of 32.
// ---------------------------------------------------------------------------
__global__ void __launch_bounds__(256, 3) fwd_gemm(
    const float* __restrict__ x,
    const float* __restrict__ Vfr, const float* __restrict__ Vfi)
{
    int p0 = blockIdx.x * 64;
    int b  = blockIdx.y;
    int s  = blockIdx.z;

    __shared__ float xs[32][68];    // [n_local][c]
    __shared__ float vb[32][132];   // [n_local][{re,im} x 64 p_local]

    int t = threadIdx.x;
    int tx = t & 15, ty = t >> 4;

    u64 acc[4][4];
    #pragma unroll
    for (int i = 0; i < 4; i++)
        #pragma unroll
        for (int j = 0; j < 4; j++) acc[i][j] = 0ULL;

    const float* xb = x + (size_t)b * Cn * Nn;
    int nl = t & 31, r0 = t >> 5;

    int kbeg = s * 1024, kend = kbeg + 1024;
    for (int k0 = kbeg; k0 < kend; k0 += 32) {
        #pragma unroll
        for (int it = 0; it < 8; it++) {
            int c = r0 + it * 8;
            xs[nl][c] = xb[c * Nn + k0 + nl];
        }
        #pragma unroll
        for (int it = 0; it < 8; it++) {
            int pl = r0 + it * 8;
            int p  = p0 + pl;
            int f  = (p >> 5) * 63 + (p & 31);
            size_t src = (size_t)f * Nn + k0 + nl;
            *(float2*)&vb[nl][2 * pl] = make_float2(Vfr[src], Vfi[src]);
        }
        __syncthreads();

        #pragma unroll
        for (int k = 0; k < 32; k++) {
            float4 a = *(const float4*)&xs[k][ty * 4];
            u64 a2[4] = {dup2(a.x), dup2(a.y), dup2(a.z), dup2(a.w)};
            const u64* bp = (const u64*)&vb[k][tx * 8];
            u64 b0 = bp[0], b1 = bp[1], b2 = bp[2], b3 = bp[3];
            #pragma unroll
            for (int i = 0; i < 4; i++) {
                acc[i][0] = fma2(a2[i], b0, acc[i][0]);
                acc[i][1] = fma2(a2[i], b1, acc[i][1]);
                acc[i][2] = fma2(a2[i], b2, acc[i][2]);
                acc[i][3] = fma2(a2[i], b3, acc[i][3]);
            }
        }
        __syncthreads();
    }

    #pragma unroll
    for (int i = 0; i < 4; i++) {
        int c = ty * 4 + i;
        size_t base = (size_t)s * BCP + ((size_t)b * Cn + c) * Pn + p0 + tx * 4;
        float2 v0 = unp2(acc[i][0]), v1 = unp2(acc[i][1]);
        float2 v2 = unp2(acc[i][2]), v3 = unp2(acc[i][3]);
        *(float4*)&g_yp_re[base] = make_float4(v0.x, v1.x, v2.x, v3.x);
        *(float4*)&g_yp_im[base] = make_float4(v0.y, v1.y, v2.y, v3.y);
    }
}

// ---------------------------------------------------------------------------
// Stage C+D: channel mix + phi modulation + Hermitian write.
// b-pair batching: grid (64, 4) = (x, b-group); each block does b = 2*bg, 2*bg+1.
// Sums the 2 fwd split-K partials while reading.
// ---------------------------------------------------------------------------
__global__ void __launch_bounds__(256) mode_mix(
    const float* __restrict__ w1r, const float* __restrict__ w1i,
    const float* __restrict__ w2r, const float* __restrict__ w2i)
{
    int x  = blockIdx.x, bg = blockIdx.y;
    int t  = threadIdx.x;
    int y  = t & 31;
    int o_base = (t >> 5) * 8;
    int xl = x & 31;
    int p  = x * 32 + y;
    int b0 = bg * 2;

    const float* wr = (x < 32) ? w1r : w2r;
    const float* wi = (x < 32) ? w1i : w2i;

    float sR[2][8] = {}, sI[2][8] = {};

    for (int i = 0; i < Cn; i++) {
        float inR[2], inI[2];
        #pragma unroll
        for (int bb = 0; bb < 2; bb++) {
            size_t yb = ((size_t)(b0 + bb) * Cn + i) * Pn + p;
            inR[bb] = g_yp_re[yb] + g_yp_re[BCP + yb];
            inI[bb] = g_yp_im[yb] + g_yp_im[BCP + yb];
        }
        size_t wbase = (((size_t)i * 64 + o_base) * 32 + xl) * 32 + y;
        #pragma unroll
        for (int j = 0; j < 8; j++) {
            float wre = __ldg(&wr[wbase + (size_t)j * 1024]);
            float wim = __ldg(&wi[wbase + (size_t)j * 1024]);
            #pragma unroll
            for (int bb = 0; bb < 2; bb++) {
                sR[bb][j] += wre * inR[bb] - wim * inI[bb];
                sI[bb][j] += wre * inI[bb] + wim * inR[bb];
            }
        }
    }

    #pragma unroll
    for (int bb = 0; bb < 2; bb++) {
        int b = b0 + bb;
        float phr = g_phi_re[(b * 64 + x) * 32 + y];
        float phm = g_phi_im[(b * 64 + x) * 32 + y];

        #pragma unroll
        for (int j = 0; j < 8; j++) {
            int o = o_base + j;
            float oR = phr * sR[bb][j] - phm * sI[bb][j];
            float oI = phr * sI[bb][j] + phm * sR[bb][j];
            size_t d1 = ((size_t)b * MFREQ + p) * Cn + o;
            g_xf_re[d1] = oR;
            g_xf_im[d1] = oI;
            if (p >= 64) {  // uniform per block (x >= 2)
                int k2 = 4095 - p;
                size_t d2 = ((size_t)b * MFREQ + k2) * Cn + (63 - o);
                g_xf_re[d2] = oR;
                g_xf_im[d2] = -oI;
            }
        }
    }
}

// ---------------------------------------------------------------------------
// Stage E: inverse NUFT, real part, packed complex FFMA2.
// Split-K = 4: blockIdx.z = s handles k in [s*1024, min(4032, s*1024+1024)).
// grid (32, 8, 4); 256 threads; 64c x 64n tile; partials to g_op (unscaled).
// ---------------------------------------------------------------------------
__global__ void __launch_bounds__(256, 3) inv_gemm(
    const float* __restrict__ Vir, const float* __restrict__ Vii)
{
    int n0 = blockIdx.x * 64;
    int b  = blockIdx.y;
    int s  = blockIdx.z;

    __shared__ float av[32][132];   // [k_local][{re,im} x 64 n_local]
    __shared__ float xv[32][132];   // [k_local][{re,-im} x 64 c]

    int t = threadIdx.x;
    int tx = t & 15, ty = t >> 4;

    u64 acc[4][4];
    #pragma unroll
    for (int i = 0; i < 4; i++)
        #pragma unroll
        for (int j = 0; j < 4; j++) acc[i][j] = 0ULL;

    int kl = t & 31, r0 = t >> 5;
    int cc = t & 63, kr0 = t >> 6;   // 0..3

    int kbeg = s * 1024;
    int kend = (s == 3) ? MFREQ : kbeg + 1024;   // last split: 960
    for (int k0 = kbeg; k0 < kend; k0 += 32) {
        #pragma unroll
        for (int it = 0; it < 8; it++) {
            int nr = r0 + it * 8;
            size_t src = (size_t)(n0 + nr) * MFREQ + k0 + kl;
            *(float2*)&av[kl][2 * nr] = make_float2(Vir[src], Vii[src]);
        }
        #pragma unroll
        for (int it = 0; it < 8; it++) {
            int kr = kr0 + it * 4;
            size_t src = ((size_t)b * MFREQ + k0 + kr) * Cn + cc;
            *(float2*)&xv[kr][2 * cc] = make_float2(g_xf_re[src], -g_xf_im[src]);
        }
        __syncthreads();

        #pragma unroll
        for (int k = 0; k < 32; k++) {
            const u64* cp = (const u64*)&xv[k][ty * 8];
            const u64* np = (const u64*)&av[k][tx * 8];
            u64 c0 = cp[0], c1 = cp[1], c2 = cp[2], c3 = cp[3];
            u64 m0 = np[0], m1 = np[1], m2 = np[2], m3 = np[3];
            acc[0][0] = fma2(c0, m0, acc[0][0]);
            acc[0][1] = fma2(c0, m1, acc[0][1]);
            acc[0][2] = fma2(c0, m2, acc[0][2]);
            acc[0][3] = fma2(c0, m3, acc[0][3]);
            acc[1][0] = fma2(c1, m0, acc[1][0]);
            acc[1][1] = fma2(c1, m1, acc[1][1]);
            acc[1][2] = fma2(c1, m2, acc[1][2]);
            acc[1][3] = fma2(c1, m3, acc[1][3]);
            acc[2][0] = fma2(c2, m0, acc[2][0]);
            acc[2][1] = fma2(c2, m1, acc[2][1]);
            acc[2][2] = fma2(c2, m2, acc[2][2]);
            acc[2][3] = fma2(c2, m3, acc[2][3]);
            acc[3][0] = fma2(c3, m0, acc[3][0]);
            acc[3][1] = fma2(c3, m1, acc[3][1]);
            acc[3][2] = fma2(c3, m2, acc[3][2]);
            acc[3][3] = fma2(c3, m3, acc[3][3]);
        }
        __syncthreads();
    }

    #pragma unroll
    for (int i = 0; i < 4; i++) {
        int c = ty * 4 + i;
        size_t dst = (size_t)s * BCN + ((size_t)b * Cn + c) * Nn + n0 + tx * 4;
        float2 v0 = unp2(acc[i][0]), v1 = unp2(acc[i][1]);
        float2 v2 = unp2(acc[i][2]), v3 = unp2(acc[i][3]);
        *(float4*)&g_op[dst] = make_float4(v0.x + v0.y, v1.x + v1.y,
                                           v2.x + v2.y, v3.x + v3.y);
    }
}

// ---------------------------------------------------------------------------
// Stage F: reduce the 4 inv split-K partials, apply 2/N scale.
// grid 1024, 256 threads, float4 per thread.
// ---------------------------------------------------------------------------
__global__ void __launch_bounds__(256) inv_reduce(float* __restrict__ out)
{
    const float s = 2.0f / (float)Nn;
    size_t i = ((size_t)blockIdx.x * 256 + threadIdx.x) * 4;
    float4 a = *(const float4*)&g_op[i];
    float4 b = *(const float4*)&g_op[BCN + i];
    float4 c = *(const float4*)&g_op[2 * (size_t)BCN + i];
    float4 d = *(const float4*)&g_op[3 * (size_t)BCN + i];
    *(float4*)&out[i] = make_float4((a.x + b.x + c.x + d.x) * s,
                                    (a.y + b.y + c.y + d.y) * s,
                                    (a.z + b.z + c.z + d.z) * s,
                                    (a.w + b.w + c.w + d.w) * s);
}

// ---------------------------------------------------------------------------
extern "C" void kernel_launch(void* const* d_in, const int* in_sizes, int n_in,
                              void* d_out, int out_size)
{
    const float* x    = (const float*)d_in[0];
    const float* emb  = (const float*)d_in[1];
    const float* Vfr  = (const float*)d_in[2];
    const float* Vfi  = (const float*)d_in[3];
    const float* Vir  = (const float*)d_in[4];
    const float* Vii  = (const float*)d_in[5];
    const float* w1r  = (const float*)d_in[6];
    const float* w1i  = (const float*)d_in[7];
    const float* w2r  = (const float*)d_in[8];
    const float* w2i  = (const float*)d_in[9];
    const float* m1r  = (const float*)d_in[10];
    const float* m1i  = (const float*)d_in[11];
    const float* m2r  = (const float*)d_in[12];
    const float* m2i  = (const float*)d_in[13];
    float* out = (float*)d_out;

    phi_kernel<<<dim3(64, 8), 256>>>(emb, m1r, m1i, m2r, m2i);
    fwd_gemm  <<<dim3(32, 8, 2), 256>>>(x, Vfr, Vfi);
    mode_mix  <<<dim3(64, 4), 256>>>(w1r, w1i, w2r, w2i);
    inv_gemm  <<<dim3(32, 8, 4), 256>>>(Vir, Vii);
    inv_reduce<<<1024, 256>>>(out);
}

// round 10
// speedup vs baseline: 1.8001x; 1.7038x over previous
#include <cuda_runtime.h>
#include <cuda_bf16.h>
#include <cstdint>

// Problem constants
#define Bn   8
#define Cn   64
#define Nn   2048
#define EMB  256
#define MFREQ 4032
#define Pn   2048            // 2*m*m used modes
#define KCAT 8064            // concatenated K for inverse (re|im)
#define MFWD 4096            // concatenated M for forward ([re;im] x 2048p)

// ---------------------------------------------------------------------------
// Scratch (device globals; no allocation allowed)
// ---------------------------------------------------------------------------
__device__ float g_phi_re[Bn * 64 * 32];
__device__ float g_phi_im[Bn * 64 * 32];
__device__ float g_yf[(size_t)Bn * MFWD * Cn];                         // [b][row][c]
__device__ __align__(16) __nv_bfloat16 g_xh[(size_t)Bn * Cn * Nn];     // [b][c][n]
__device__ __align__(16) __nv_bfloat16 g_xl[(size_t)Bn * Cn * Nn];
__device__ __align__(16) __nv_bfloat16 g_vfh[(size_t)MFWD * Nn];       // [row][n]
__device__ __align__(16) __nv_bfloat16 g_vfl[(size_t)MFWD * Nn];
__device__ __align__(16) __nv_bfloat16 g_xfh[(size_t)Bn * Cn * KCAT];  // [b][c][kk]
__device__ __align__(16) __nv_bfloat16 g_xfl[(size_t)Bn * Cn * KCAT];
__device__ __align__(16) __nv_bfloat16 g_vih[(size_t)Nn * KCAT];       // [n][kk]
__device__ __align__(16) __nv_bfloat16 g_vil[(size_t)Nn * KCAT];

// ---------------------------------------------------------------------------
// Warp-MMA helpers (plain compute_103 ISA: ldmatrix + mma.sync bf16)
// ---------------------------------------------------------------------------
__device__ __forceinline__ uint32_t smem_to_u32(const void* p) {
    uint32_t a;
    asm("{ .reg .u64 t; cvta.to.shared.u64 t, %1; cvt.u32.u64 %0, t; }" : "=r"(a) : "l"(p));
    return a;
}
__device__ __forceinline__ void ldsm_x4(uint32_t* r, uint32_t addr) {
    asm volatile("ldmatrix.sync.aligned.m8n8.x4.shared.b16 {%0,%1,%2,%3}, [%4];"
                 : "=r"(r[0]), "=r"(r[1]), "=r"(r[2]), "=r"(r[3]) : "r"(addr));
}
__device__ __forceinline__ void mma_bf16(float* d, const uint32_t* a,
                                         uint32_t b0, uint32_t b1) {
    asm volatile("mma.sync.aligned.m16n8k16.row.col.f32.bf16.bf16.f32 "
                 "{%0,%1,%2,%3}, {%4,%5,%6,%7}, {%8,%9}, {%0,%1,%2,%3};"
                 : "+f"(d[0]), "+f"(d[1]), "+f"(d[2]), "+f"(d[3])
                 : "r"(a[0]), "r"(a[1]), "r"(a[2]), "r"(a[3]), "r"(b0), "r"(b1));
}

// smem stage geometry (shared by both MMA kernels)
#define KPAD_B   80                       // 32 bf16 + 8 pad = 80 bytes/row
#define OFF_AH   0
#define OFF_AL   (128 * KPAD_B)           // 10240
#define OFF_BH   (2 * 128 * KPAD_B)       // 20480
#define OFF_BL   (OFF_BH + 64 * KPAD_B)   // 25600
#define ST_BYTES (OFF_BL + 64 * KPAD_B)   // 30720
#define SMEM_DYN (2 * ST_BYTES)           // 61440

// ---------------------------------------------------------------------------
// Stage B: phi[b][x][y] = sum_e m[...] * emb[b][e]  (re & im)
// ---------------------------------------------------------------------------
__global__ void __launch_bounds__(256) phi_kernel(
    const float* __restrict__ emb,
    const float* __restrict__ m1r, const float* __restrict__ m1i,
    const float* __restrict__ m2r, const float* __restrict__ m2i)
{
    int x = blockIdx.x, b = blockIdx.y;
    __shared__ float es[EMB];
    int t = threadIdx.x;
    es[t] = emb[b * EMB + t];
    __syncthreads();

    int w = t >> 5, lane = t & 31;
    int xl = x & 31;
    const float* mr = (x < 32) ? m1r : m2r;
    const float* mi = (x < 32) ? m1i : m2i;

    #pragma unroll
    for (int task = 0; task < 8; task++) {
        int tid = w * 8 + task;
        int y = tid & 31;
        const float* src = ((tid < 32) ? mr : mi) + (xl * 32 + y) * EMB;
        float s = 0.f;
        #pragma unroll
        for (int q = 0; q < 8; q++) {
            int e = lane + q * 32;
            s += src[e] * es[e];
        }
        #pragma unroll
        for (int off = 16; off; off >>= 1)
            s += __shfl_down_sync(0xffffffffu, s, off);
        if (lane == 0) {
            float* dst = (tid < 32) ? g_phi_re : g_phi_im;
            dst[(b * 64 + x) * 32 + y] = s;
        }
    }
}

// ---------------------------------------------------------------------------
// Input conversions to bf16 hi/lo
// ---------------------------------------------------------------------------
__global__ void __launch_bounds__(128) x_convert(const float* __restrict__ x)
{
    size_t i = (size_t)blockIdx.x * 128 + threadIdx.x;   // over Bn*Cn*Nn
    float v = x[i];
    __nv_bfloat16 h = __float2bfloat16(v);
    g_xh[i] = h;
    g_xl[i] = __float2bfloat16(v - __bfloat162float(h));
}

// rows 0..2047: Vf_re[f(p)], rows 2048..4095: Vf_im[f(p)]
__global__ void __launch_bounds__(128) vf_convert(
    const float* __restrict__ Vfr, const float* __restrict__ Vfi)
{
    int n   = blockIdx.x * 128 + threadIdx.x;
    int row = blockIdx.y;
    int p   = row & 2047;
    int f   = (p >> 5) * 63 + (p & 31);
    float v = (row < 2048) ? Vfr[(size_t)f * Nn + n] : Vfi[(size_t)f * Nn + n];
    size_t i = (size_t)row * Nn + n;
    __nv_bfloat16 h = __float2bfloat16(v);
    g_vfh[i] = h;
    g_vfl[i] = __float2bfloat16(v - __bfloat162float(h));
}

__global__ void __launch_bounds__(128) vi_convert(
    const float* __restrict__ Vir, const float* __restrict__ Vii)
{
    int kk = blockIdx.x * 128 + threadIdx.x;
    int n  = blockIdx.y;
    float v = (kk < 4032) ? Vir[(size_t)n * MFREQ + kk]
                          : -Vii[(size_t)n * MFREQ + kk - 4032];
    size_t i = (size_t)n * KCAT + kk;
    __nv_bfloat16 h = __float2bfloat16(v);
    g_vih[i] = h;
    g_vil[i] = __float2bfloat16(v - __bfloat162float(h));
}

// ---------------------------------------------------------------------------
// Stage A: forward NUFT via mma.sync.  yT[row][c] = Vfcat[row][n] @ x[b][c][n]^T
// grid (32, 8) = (row-tile, b); 256 thr / 8 warps; D[128row x 64c]; K=2048.
// ---------------------------------------------------------------------------
__global__ void __launch_bounds__(256, 1) fwd_mma_warp()
{
    extern __shared__ char smem[];
    uint32_t sb = smem_to_u32(smem);
    int t    = threadIdx.x;
    int lane = t & 31, wid = t >> 5;
    int wr   = wid & 3;
    int wc   = wid >> 2;
    int row0 = blockIdx.x * 128;
    int b    = blockIdx.y;

    const __nv_bfloat16* vfA[2] = {g_vfh, g_vfl};
    const __nv_bfloat16* xB[2]  = {g_xh, g_xl};

    float acc[2][4][4];
    #pragma unroll
    for (int i = 0; i < 2; i++)
        #pragma unroll
        for (int j = 0; j < 4; j++)
            #pragma unroll
            for (int v = 0; v < 4; v++) acc[i][j][v] = 0.f;

    auto load_stage = [&](int s, int kk0) {
        char* stage = smem + s * ST_BYTES;
        #pragma unroll
        for (int i = 0; i < 6; i++) {
            int idx = t + i * 256;
            const uint4* src;
            uint32_t off;
            if (idx < 1024) {                 // A: Vfcat rows (hi then lo)
                int comp = idx >> 9, r = (idx >> 2) & 127, g = idx & 3;
                src = (const uint4*)(vfA[comp] + (size_t)(row0 + r) * Nn + kk0 + g * 8);
                off = (comp ? OFF_AL : OFF_AH) + r * KPAD_B + g * 16;
            } else {                          // B: x rows (hi then lo)
                int j = idx - 1024;
                int comp = j >> 8, r = (j >> 2) & 63, g = j & 3;
                src = (const uint4*)(xB[comp] + ((size_t)b * Cn + r) * Nn + kk0 + g * 8);
                off = (comp ? OFF_BL : OFF_BH) + r * KPAD_B + g * 16;
            }
            *(uint4*)(stage + off) = *src;
        }
    };

    load_stage(0, 0);
    __syncthreads();

    int lrow = lane & 15;
    int lkh  = lane >> 4;

    for (int ch = 0; ch < 64; ch++) {
        int s = ch & 1;
        if (ch + 1 < 64) load_stage(s ^ 1, (ch + 1) * 32);

        uint32_t st = sb + s * ST_BYTES;
        #pragma unroll
        for (int ks = 0; ks < 2; ks++) {
            uint32_t kofs = ks * 32 + lkh * 16;

            uint32_t ah[2][4], al[2][4];
            #pragma unroll
            for (int mf = 0; mf < 2; mf++) {
                uint32_t rowb = (wr * 32 + mf * 16 + lrow) * KPAD_B + kofs;
                ldsm_x4(ah[mf], st + OFF_AH + rowb);
                ldsm_x4(al[mf], st + OFF_AL + rowb);
            }
            uint32_t bh[2][4], bl[2][4];
            #pragma unroll
            for (int pr = 0; pr < 2; pr++) {
                uint32_t rowb = (wc * 32 + pr * 16 + lrow) * KPAD_B + kofs;
                ldsm_x4(bh[pr], st + OFF_BH + rowb);
                ldsm_x4(bl[pr], st + OFF_BL + rowb);
            }

            #pragma unroll
            for (int mf = 0; mf < 2; mf++)
                #pragma unroll
                for (int nf = 0; nf < 4; nf++) {
                    int pr = nf >> 1, wch = nf & 1;
                    uint32_t bh0 = bh[pr][wch], bh1 = bh[pr][wch + 2];
                    uint32_t bl0 = bl[pr][wch], bl1 = bl[pr][wch + 2];
                    mma_bf16(acc[mf][nf], ah[mf], bh0, bh1);
                    mma_bf16(acc[mf][nf], ah[mf], bl0, bl1);
                    mma_bf16(acc[mf][nf], al[mf], bh0, bh1);
                }
        }
        __syncthreads();
    }

    // epilogue: D[row][c] -> g_yf[b][row][c]
    int g  = lane >> 2;
    int cl = (lane & 3) * 2;
    #pragma unroll
    for (int mf = 0; mf < 2; mf++) {
        int row = row0 + wr * 32 + mf * 16 + g;
        #pragma unroll
        for (int nf = 0; nf < 4; nf++) {
            int c = wc * 32 + nf * 8 + cl;
            size_t o0 = ((size_t)b * MFWD + row) * Cn + c;
            g_yf[o0]           = acc[mf][nf][0];
            g_yf[o0 + 1]       = acc[mf][nf][1];
            g_yf[o0 + 8 * Cn]     = acc[mf][nf][2];
            g_yf[o0 + 8 * Cn + 1] = acc[mf][nf][3];
        }
    }
}

// ---------------------------------------------------------------------------
// Stage C+D: channel mix + modulation + Hermitian; writes bf16 hi/lo xf-cat.
// y read from g_yf[b][row][c]: row<2048 = re, row>=2048 = im.
// ---------------------------------------------------------------------------
__device__ __forceinline__ void write_split(size_t idx, float v) {
    __nv_bfloat16 h = __float2bfloat16(v);
    g_xfh[idx] = h;
    g_xfl[idx] = __float2bfloat16(v - __bfloat162float(h));
}

__global__ void __launch_bounds__(256) mode_mix(
    const float* __restrict__ w1r, const float* __restrict__ w1i,
    const float* __restrict__ w2r, const float* __restrict__ w2i)
{
    int x  = blockIdx.x, bg = blockIdx.y;
    int t  = threadIdx.x;
    int y  = t & 31;
    int o_base = (t >> 5) * 8;
    int xl = x & 31;
    int p  = x * 32 + y;
    int b0 = bg * 2;

    const float* wr = (x < 32) ? w1r : w2r;
    const float* wi = (x < 32) ? w1i : w2i;

    float sR[2][8] = {}, sI[2][8] = {};

    for (int i = 0; i < Cn; i++) {
        float inR[2], inI[2];
        #pragma unroll
        for (int bb = 0; bb < 2; bb++) {
            size_t yb = ((size_t)(b0 + bb) * MFWD + p) * Cn + i;
            inR[bb] = g_yf[yb];
            inI[bb] = g_yf[yb + (size_t)2048 * Cn];
        }
        size_t wbase = (((size_t)i * 64 + o_base) * 32 + xl) * 32 + y;
        #pragma unroll
        for (int j = 0; j < 8; j++) {
            float wre = __ldg(&wr[wbase + (size_t)j * 1024]);
            float wim = __ldg(&wi[wbase + (size_t)j * 1024]);
            #pragma unroll
            for (int bb = 0; bb < 2; bb++) {
                sR[bb][j] += wre * inR[bb] - wim * inI[bb];
                sI[bb][j] += wre * inI[bb] + wim * inR[bb];
            }
        }
    }

    #pragma unroll
    for (int bb = 0; bb < 2; bb++) {
        int b = b0 + bb;
        float phr = g_phi_re[(b * 64 + x) * 32 + y];
        float phm = g_phi_im[(b * 64 + x) * 32 + y];

        #pragma unroll
        for (int j = 0; j < 8; j++) {
            int o = o_base + j;
            float oR = phr * sR[bb][j] - phm * sI[bb][j];
            float oI = phr * sI[bb][j] + phm * sR[bb][j];
            size_t c1 = ((size_t)b * Cn + o) * KCAT;
            write_split(c1 + p, oR);
            write_split(c1 + 4032 + p, oI);
            if (p >= 64) {
                int k2 = 4095 - p;
                size_t c2 = ((size_t)b * Cn + (63 - o)) * KCAT;
                write_split(c2 + k2, oR);
                write_split(c2 + 4032 + k2, -oI);
            }
        }
    }
}

// ---------------------------------------------------------------------------
// Stage E: inverse NUFT via mma.sync (bf16 hi/lo, 3 products).
// grid (16, 8) = (n-tile, b); 256 thr / 8 warps; D[128n x 64c]; K=8064, 252x32.
// ---------------------------------------------------------------------------
__global__ void __launch_bounds__(256, 1) inv_mma_warp(float* __restrict__ out)
{
    extern __shared__ char smem[];
    uint32_t sb = smem_to_u32(smem);
    int t    = threadIdx.x;
    int lane = t & 31, wid = t >> 5;
    int wr   = wid & 3;        // n-dim warp row (4 x 32)
    int wc   = wid >> 2;       // c-dim warp col (2 x 32)
    int n0   = blockIdx.x * 128;
    int b    = blockIdx.y;

    const __nv_bfloat16* viA[2] = {g_vih, g_vil};
    const __nv_bfloat16* xfB[2] = {g_xfh, g_xfl};

    float acc[2][4][4];
    #pragma unroll
    for (int i = 0; i < 2; i++)
        #pragma unroll
        for (int j = 0; j < 4; j++)
            #pragma unroll
            for (int v = 0; v < 4; v++) acc[i][j][v] = 0.f;

    auto load_stage = [&](int s, int kk0) {
        char* stage = smem + s * ST_BYTES;
        #pragma unroll
        for (int i = 0; i < 6; i++) {
            int idx = t + i * 256;
            const uint4* src;
            uint32_t off;
            if (idx < 1024) {                 // A: Vi rows (hi then lo)
                int comp = idx >> 9, r = (idx >> 2) & 127, g = idx & 3;
                src = (const uint4*)(viA[comp] + (size_t)(n0 + r) * KCAT + kk0 + g * 8);
                off = (comp ? OFF_AL : OFF_AH) + r * KPAD_B + g * 16;
            } else {                          // B: xf rows (hi then lo)
                int j = idx - 1024;
                int comp = j >> 8, r = (j >> 2) & 63, g = j & 3;
                src = (const uint4*)(xfB[comp] + ((size_t)b * Cn + r) * KCAT + kk0 + g * 8);
                off = (comp ? OFF_BL : OFF_BH) + r * KPAD_B + g * 16;
            }
            *(uint4*)(stage + off) = *src;
        }
    };

    load_stage(0, 0);
    __syncthreads();

    int lrow = lane & 15;
    int lkh  = lane >> 4;

    for (int ch = 0; ch < 252; ch++) {
        int s = ch & 1;
        if (ch + 1 < 252) load_stage(s ^ 1, (ch + 1) * 32);

        uint32_t st = sb + s * ST_BYTES;
        #pragma unroll
        for (int ks = 0; ks < 2; ks++) {
            uint32_t kofs = ks * 32 + lkh * 16;

            uint32_t ah[2][4], al[2][4];
            #pragma unroll
            for (int mf = 0; mf < 2; mf++) {
                uint32_t rowb = (wr * 32 + mf * 16 + lrow) * KPAD_B + kofs;
                ldsm_x4(ah[mf], st + OFF_AH + rowb);
                ldsm_x4(al[mf], st + OFF_AL + rowb);
            }
            uint32_t bh[2][4], bl[2][4];
            #pragma unroll
            for (int pr = 0; pr < 2; pr++) {
                uint32_t rowb = (wc * 32 + pr * 16 + lrow) * KPAD_B + kofs;
                ldsm_x4(bh[pr], st + OFF_BH + rowb);
                ldsm_x4(bl[pr], st + OFF_BL + rowb);
            }

            #pragma unroll
            for (int mf = 0; mf < 2; mf++)
                #pragma unroll
                for (int nf = 0; nf < 4; nf++) {
                    int pr = nf >> 1, wch = nf & 1;
                    uint32_t bh0 = bh[pr][wch], bh1 = bh[pr][wch + 2];
                    uint32_t bl0 = bl[pr][wch], bl1 = bl[pr][wch + 2];
                    mma_bf16(acc[mf][nf], ah[mf], bh0, bh1);   // hi*hi
                    mma_bf16(acc[mf][nf], ah[mf], bl0, bl1);   // hi*lo
                    mma_bf16(acc[mf][nf], al[mf], bh0, bh1);   // lo*hi
                }
        }
        __syncthreads();
    }

    // epilogue: D[n][c] fragments -> out[b][c][n], scaled by 2/N
    const float sc = 2.0f / (float)Nn;
    int g  = lane >> 2;
    int cl = (lane & 3) * 2;
    #pragma unroll
    for (int mf = 0; mf < 2; mf++) {
        int nbase = n0 + wr * 32 + mf * 16 + g;
        #pragma unroll
        for (int nf = 0; nf < 4; nf++) {
            int c = wc * 32 + nf * 8 + cl;
            size_t o0 = ((size_t)b * Cn + c) * Nn;
            out[o0 + nbase]          = acc[mf][nf][0] * sc;
            out[o0 + Nn + nbase]     = acc[mf][nf][1] * sc;
            out[o0 + nbase + 8]      = acc[mf][nf][2] * sc;
            out[o0 + Nn + nbase + 8] = acc[mf][nf][3] * sc;
        }
    }
}

// ---------------------------------------------------------------------------
extern "C" void kernel_launch(void* const* d_in, const int* in_sizes, int n_in,
                              void* d_out, int out_size)
{
    const float* x    = (const float*)d_in[0];
    const float* emb  = (const float*)d_in[1];
    const float* Vfr  = (const float*)d_in[2];
    const float* Vfi  = (const float*)d_in[3];
    const float* Vir  = (const float*)d_in[4];
    const float* Vii  = (const float*)d_in[5];
    const float* w1r  = (const float*)d_in[6];
    const float* w1i  = (const float*)d_in[7];
    const float* w2r  = (const float*)d_in[8];
    const float* w2i  = (const float*)d_in[9];
    const float* m1r  = (const float*)d_in[10];
    const float* m1i  = (const float*)d_in[11];
    const float* m2r  = (const float*)d_in[12];
    const float* m2i  = (const float*)d_in[13];
    float* out = (float*)d_out;

    cudaFuncSetAttribute(fwd_mma_warp, cudaFuncAttributeMaxDynamicSharedMemorySize, SMEM_DYN);
    cudaFuncSetAttribute(inv_mma_warp, cudaFuncAttributeMaxDynamicSharedMemorySize, SMEM_DYN);

    phi_kernel  <<<dim3(64, 8), 256>>>(emb, m1r, m1i, m2r, m2i);
    x_convert   <<<dim3(8192), 128>>>(x);
    vf_convert  <<<dim3(16, 4096), 128>>>(Vfr, Vfi);
    vi_convert  <<<dim3(63, 2048), 128>>>(Vir, Vii);
    fwd_mma_warp<<<dim3(32, 8), 256, SMEM_DYN>>>();
    mode_mix    <<<dim3(64, 4), 256>>>(w1r, w1i, w2r, w2i);
    inv_mma_warp<<<dim3(16, 8), 256, SMEM_DYN>>>(out);
}

// round 15
// speedup vs baseline: 2.0715x; 1.1507x over previous
#include <cuda_runtime.h>
#include <cuda_bf16.h>
#include <cstdint>

// Problem constants
#define Bn   8
#define Cn   64
#define Nn   2048
#define EMB  256
#define MFREQ 4032
#define Pn   2048
#define KCAT 8064            // concatenated K for inverse (re|im)
#define MFWD 4096            // concatenated M for forward ([re;im] x 2048p)
#define BCN  (Bn * Cn * Nn)  // 1,048,576

// ---------------------------------------------------------------------------
// Scratch (device globals; no allocation allowed)
// ---------------------------------------------------------------------------
__device__ float g_phi_re[Bn * 64 * 32];
__device__ float g_phi_im[Bn * 64 * 32];
__device__ float g_yf[(size_t)Bn * MFWD * Cn];                         // [b][row][c]
__device__ float g_op[2 * BCN];                                        // inv split-K partials
__device__ __align__(16) __nv_bfloat16 g_xh[(size_t)Bn * Cn * Nn];     // [b][c][n]
__device__ __align__(16) __nv_bfloat16 g_xl[(size_t)Bn * Cn * Nn];
__device__ __align__(16) __nv_bfloat16 g_vfh[(size_t)MFWD * Nn];       // [row][n]
__device__ __align__(16) __nv_bfloat16 g_vfl[(size_t)MFWD * Nn];
__device__ __align__(16) __nv_bfloat16 g_xfh[(size_t)Bn * Cn * KCAT];  // [b][c][kk]
__device__ __align__(16) __nv_bfloat16 g_xfl[(size_t)Bn * Cn * KCAT];
__device__ __align__(16) __nv_bfloat16 g_vih[(size_t)Nn * KCAT];       // [n][kk]
__device__ __align__(16) __nv_bfloat16 g_vil[(size_t)Nn * KCAT];

// ---------------------------------------------------------------------------
// Warp-MMA helpers
// ---------------------------------------------------------------------------
__device__ __forceinline__ uint32_t smem_to_u32(const void* p) {
    uint32_t a;
    asm("{ .reg .u64 t; cvta.to.shared.u64 t, %1; cvt.u32.u64 %0, t; }" : "=r"(a) : "l"(p));
    return a;
}
__device__ __forceinline__ void ldsm_x4(uint32_t* r, uint32_t addr) {
    asm volatile("ldmatrix.sync.aligned.m8n8.x4.shared.b16 {%0,%1,%2,%3}, [%4];"
                 : "=r"(r[0]), "=r"(r[1]), "=r"(r[2]), "=r"(r[3]) : "r"(addr));
}
__device__ __forceinline__ void mma_bf16(float* d, const uint32_t* a,
                                         uint32_t b0, uint32_t b1) {
    asm volatile("mma.sync.aligned.m16n8k16.row.col.f32.bf16.bf16.f32 "
                 "{%0,%1,%2,%3}, {%4,%5,%6,%7}, {%8,%9}, {%0,%1,%2,%3};"
                 : "+f"(d[0]), "+f"(d[1]), "+f"(d[2]), "+f"(d[3])
                 : "r"(a[0]), "r"(a[1]), "r"(a[2]), "r"(a[3]), "r"(b0), "r"(b1));
}

// smem stage geometry (shared by both MMA kernels)
#define KPAD_B   80
#define OFF_AH   0
#define OFF_AL   (128 * KPAD_B)
#define OFF_BH   (2 * 128 * KPAD_B)
#define OFF_BL   (OFF_BH + 64 * KPAD_B)
#define ST_BYTES (OFF_BL + 64 * KPAD_B)
#define SMEM_DYN (2 * ST_BYTES)

// bf16 hi/lo split of 8 contiguous floats -> two uint4 stores
__device__ __forceinline__ void split8(const float* v, __nv_bfloat16* dh, __nv_bfloat16* dl) {
    __nv_bfloat16 hs[8], ls[8];
    #pragma unroll
    for (int q = 0; q < 8; q++) {
        __nv_bfloat16 h = __float2bfloat16(v[q]);
        hs[q] = h;
        ls[q] = __float2bfloat16(v[q] - __bfloat162float(h));
    }
    *(uint4*)dh = *(const uint4*)hs;
    *(uint4*)dl = *(const uint4*)ls;
}

// ---------------------------------------------------------------------------
// Stage B: phi
// ---------------------------------------------------------------------------
__global__ void __launch_bounds__(256) phi_kernel(
    const float* __restrict__ emb,
    const float* __restrict__ m1r, const float* __restrict__ m1i,
    const float* __restrict__ m2r, const float* __restrict__ m2i)
{
    int x = blockIdx.x, b = blockIdx.y;
    __shared__ float es[EMB];
    int t = threadIdx.x;
    es[t] = emb[b * EMB + t];
    __syncthreads();

    int w = t >> 5, lane = t & 31;
    int xl = x & 31;
    const float* mr = (x < 32) ? m1r : m2r;
    const float* mi = (x < 32) ? m1i : m2i;

    #pragma unroll
    for (int task = 0; task < 8; task++) {
        int tid = w * 8 + task;
        int y = tid & 31;
        const float* src = ((tid < 32) ? mr : mi) + (xl * 32 + y) * EMB;
        float s = 0.f;
        #pragma unroll
        for (int q = 0; q < 8; q++) {
            int e = lane + q * 32;
            s += src[e] * es[e];
        }
        #pragma unroll
        for (int off = 16; off; off >>= 1)
            s += __shfl_down_sync(0xffffffffu, s, off);
        if (lane == 0) {
            float* dst = (tid < 32) ? g_phi_re : g_phi_im;
            dst[(b * 64 + x) * 32 + y] = s;
        }
    }
}

// ---------------------------------------------------------------------------
// Vectorized input conversions (8 elems/thread, float4 in, uint4 out)
// ---------------------------------------------------------------------------
__global__ void __launch_bounds__(256) x_convert(const float* __restrict__ x)
{
    size_t i = ((size_t)blockIdx.x * 256 + threadIdx.x) * 8;   // over Bn*Cn*Nn
    float v[8];
    *(float4*)&v[0] = *(const float4*)(x + i);
    *(float4*)&v[4] = *(const float4*)(x + i + 4);
    split8(v, g_xh + i, g_xl + i);
}

__global__ void __launch_bounds__(256) vf_convert(
    const float* __restrict__ Vfr, const float* __restrict__ Vfi)
{
    size_t i   = ((size_t)blockIdx.x * 256 + threadIdx.x) * 8;  // over MFWD*Nn
    int row = (int)(i >> 11);          // /Nn
    int n   = (int)(i & 2047);
    int p   = row & 2047;
    int f   = (p >> 5) * 63 + (p & 31);
    const float* src = ((row < 2048) ? Vfr : Vfi) + (size_t)f * Nn + n;
    float v[8];
    *(float4*)&v[0] = *(const float4*)src;
    *(float4*)&v[4] = *(const float4*)(src + 4);
    split8(v, g_vfh + i, g_vfl + i);
}

__global__ void __launch_bounds__(256) vi_convert(
    const float* __restrict__ Vir, const float* __restrict__ Vii)
{
    size_t i  = ((size_t)blockIdx.x * 256 + threadIdx.x) * 8;   // over Nn*KCAT
    int n  = (int)(i / KCAT);
    int kk = (int)(i % KCAT);
    float v[8];
    if (kk < 4032) {
        const float* src = Vir + (size_t)n * MFREQ + kk;
        *(float4*)&v[0] = *(const float4*)src;
        *(float4*)&v[4] = *(const float4*)(src + 4);
    } else {
        const float* src = Vii + (size_t)n * MFREQ + (kk - 4032);
        float4 a = *(const float4*)src;
        float4 b = *(const float4*)(src + 4);
        v[0] = -a.x; v[1] = -a.y; v[2] = -a.z; v[3] = -a.w;
        v[4] = -b.x; v[5] = -b.y; v[6] = -b.z; v[7] = -b.w;
    }
    split8(v, g_vih + i, g_vil + i);
}

// ---------------------------------------------------------------------------
// Stage A: forward NUFT via mma.sync (unchanged mainloop)
// ---------------------------------------------------------------------------
__global__ void __launch_bounds__(256, 1) fwd_mma_warp()
{
    extern __shared__ char smem[];
    uint32_t sb = smem_to_u32(smem);
    int t    = threadIdx.x;
    int lane = t & 31, wid = t >> 5;
    int wr   = wid & 3;
    int wc   = wid >> 2;
    int row0 = blockIdx.x * 128;
    int b    = blockIdx.y;

    const __nv_bfloat16* vfA[2] = {g_vfh, g_vfl};
    const __nv_bfloat16* xB[2]  = {g_xh, g_xl};

    float acc[2][4][4];
    #pragma unroll
    for (int i = 0; i < 2; i++)
        #pragma unroll
        for (int j = 0; j < 4; j++)
            #pragma unroll
            for (int v = 0; v < 4; v++) acc[i][j][v] = 0.f;

    auto load_stage = [&](int s, int kk0) {
        char* stage = smem + s * ST_BYTES;
        #pragma unroll
        for (int i = 0; i < 6; i++) {
            int idx = t + i * 256;
            const uint4* src;
            uint32_t off;
            if (idx < 1024) {
                int comp = idx >> 9, r = (idx >> 2) & 127, g = idx & 3;
                src = (const uint4*)(vfA[comp] + (size_t)(row0 + r) * Nn + kk0 + g * 8);
                off = (comp ? OFF_AL : OFF_AH) + r * KPAD_B + g * 16;
            } else {
                int j = idx - 1024;
                int comp = j >> 8, r = (j >> 2) & 63, g = j & 3;
                src = (const uint4*)(xB[comp] + ((size_t)b * Cn + r) * Nn + kk0 + g * 8);
                off = (comp ? OFF_BL : OFF_BH) + r * KPAD_B + g * 16;
            }
            *(uint4*)(stage + off) = *src;
        }
    };

    load_stage(0, 0);
    __syncthreads();

    int lrow = lane & 15;
    int lkh  = lane >> 4;

    for (int ch = 0; ch < 64; ch++) {
        int s = ch & 1;
        if (ch + 1 < 64) load_stage(s ^ 1, (ch + 1) * 32);

        uint32_t st = sb + s * ST_BYTES;
        #pragma unroll
        for (int ks = 0; ks < 2; ks++) {
            uint32_t kofs = ks * 32 + lkh * 16;

            uint32_t ah[2][4], al[2][4];
            #pragma unroll
            for (int mf = 0; mf < 2; mf++) {
                uint32_t rowb = (wr * 32 + mf * 16 + lrow) * KPAD_B + kofs;
                ldsm_x4(ah[mf], st + OFF_AH + rowb);
                ldsm_x4(al[mf], st + OFF_AL + rowb);
            }
            uint32_t bh[2][4], bl[2][4];
            #pragma unroll
            for (int pr = 0; pr < 2; pr++) {
                uint32_t rowb = (wc * 32 + pr * 16 + lrow) * KPAD_B + kofs;
                ldsm_x4(bh[pr], st + OFF_BH + rowb);
                ldsm_x4(bl[pr], st + OFF_BL + rowb);
            }

            #pragma unroll
            for (int mf = 0; mf < 2; mf++)
                #pragma unroll
                for (int nf = 0; nf < 4; nf++) {
                    int pr = nf >> 1, wch = nf & 1;
                    uint32_t bh0 = bh[pr][wch], bh1 = bh[pr][wch + 2];
                    uint32_t bl0 = bl[pr][wch], bl1 = bl[pr][wch + 2];
                    mma_bf16(acc[mf][nf], ah[mf], bh0, bh1);
                    mma_bf16(acc[mf][nf], ah[mf], bl0, bl1);
                    mma_bf16(acc[mf][nf], al[mf], bh0, bh1);
                }
        }
        __syncthreads();
    }

    int g  = lane >> 2;
    int cl = (lane & 3) * 2;
    #pragma unroll
    for (int mf = 0; mf < 2; mf++) {
        int row = row0 + wr * 32 + mf * 16 + g;
        #pragma unroll
        for (int nf = 0; nf < 4; nf++) {
            int c = wc * 32 + nf * 8 + cl;
            size_t o0 = ((size_t)b * MFWD + row) * Cn + c;
            g_yf[o0]              = acc[mf][nf][0];
            g_yf[o0 + 1]          = acc[mf][nf][1];
            g_yf[o0 + 8 * Cn]     = acc[mf][nf][2];
            g_yf[o0 + 8 * Cn + 1] = acc[mf][nf][3];
        }
    }
}

// ---------------------------------------------------------------------------
// Stage C+D: channel mix + modulation + Hermitian; 4 batches per block.
// grid (64, 2) = (x, b-group of 4).
// ---------------------------------------------------------------------------
__device__ __forceinline__ void write_split(size_t idx, float v) {
    __nv_bfloat16 h = __float2bfloat16(v);
    g_xfh[idx] = h;
    g_xfl[idx] = __float2bfloat16(v - __bfloat162float(h));
}

__global__ void __launch_bounds__(256) mode_mix(
    const float* __restrict__ w1r, const float* __restrict__ w1i,
    const float* __restrict__ w2r, const float* __restrict__ w2i)
{
    int x  = blockIdx.x, bg = blockIdx.y;
    int t  = threadIdx.x;
    int y  = t & 31;
    int o_base = (t >> 5) * 8;
    int xl = x & 31;
    int p  = x * 32 + y;
    int b0 = bg * 4;

    const float* wr = (x < 32) ? w1r : w2r;
    const float* wi = (x < 32) ? w1i : w2i;

    float sR[4][8] = {}, sI[4][8] = {};

    for (int i = 0; i < Cn; i++) {
        float inR[4], inI[4];
        #pragma unroll
        for (int bb = 0; bb < 4; bb++) {
            size_t yb = ((size_t)(b0 + bb) * MFWD + p) * Cn + i;
            inR[bb] = g_yf[yb];
            inI[bb] = g_yf[yb + (size_t)2048 * Cn];
        }
        size_t wbase = (((size_t)i * 64 + o_base) * 32 + xl) * 32 + y;
        #pragma unroll
        for (int j = 0; j < 8; j++) {
            float wre = __ldg(&wr[wbase + (size_t)j * 1024]);
            float wim = __ldg(&wi[wbase + (size_t)j * 1024]);
            #pragma unroll
            for (int bb = 0; bb < 4; bb++) {
                sR[bb][j] += wre * inR[bb] - wim * inI[bb];
                sI[bb][j] += wre * inI[bb] + wim * inR[bb];
            }
        }
    }

    #pragma unroll
    for (int bb = 0; bb < 4; bb++) {
        int b = b0 + bb;
        float phr = g_phi_re[(b * 64 + x) * 32 + y];
        float phm = g_phi_im[(b * 64 + x) * 32 + y];

        #pragma unroll
        for (int j = 0; j < 8; j++) {
            int o = o_base + j;
            float oR = phr * sR[bb][j] - phm * sI[bb][j];
            float oI = phr * sI[bb][j] + phm * sR[bb][j];
            size_t c1 = ((size_t)b * Cn + o) * KCAT;
            write_split(c1 + p, oR);
            write_split(c1 + 4032 + p, oI);
            if (p >= 64) {
                int k2 = 4095 - p;
                size_t c2 = ((size_t)b * Cn + (63 - o)) * KCAT;
                write_split(c2 + k2, oR);
                write_split(c2 + 4032 + k2, -oI);
            }
        }
    }
}

// ---------------------------------------------------------------------------
// Stage E: inverse NUFT via mma.sync, split-K = 2.
// grid (16, 8, 2); K-half = 4032, 126 chunks; unscaled partials to g_op.
// ---------------------------------------------------------------------------
__global__ void __launch_bounds__(256, 1) inv_mma_warp()
{
    extern __shared__ char smem[];
    uint32_t sb = smem_to_u32(smem);
    int t    = threadIdx.x;
    int lane = t & 31, wid = t >> 5;
    int wr   = wid & 3;
    int wc   = wid >> 2;
    int n0   = blockIdx.x * 128;
    int b    = blockIdx.y;
    int sk   = blockIdx.z;
    int kbase = sk * 4032;

    const __nv_bfloat16* viA[2] = {g_vih, g_vil};
    const __nv_bfloat16* xfB[2] = {g_xfh, g_xfl};

    float acc[2][4][4];
    #pragma unroll
    for (int i = 0; i < 2; i++)
        #pragma unroll
        for (int j = 0; j < 4; j++)
            #pragma unroll
            for (int v = 0; v < 4; v++) acc[i][j][v] = 0.f;

    auto load_stage = [&](int s, int kk0) {
        char* stage = smem + s * ST_BYTES;
        #pragma unroll
        for (int i = 0; i < 6; i++) {
            int idx = t + i * 256;
            const uint4* src;
            uint32_t off;
            if (idx < 1024) {
                int comp = idx >> 9, r = (idx >> 2) & 127, g = idx & 3;
                src = (const uint4*)(viA[comp] + (size_t)(n0 + r) * KCAT + kk0 + g * 8);
                off = (comp ? OFF_AL : OFF_AH) + r * KPAD_B + g * 16;
            } else {
                int j = idx - 1024;
                int comp = j >> 8, r = (j >> 2) & 63, g = j & 3;
                src = (const uint4*)(xfB[comp] + ((size_t)b * Cn + r) * KCAT + kk0 + g * 8);
                off = (comp ? OFF_BL : OFF_BH) + r * KPAD_B + g * 16;
            }
            *(uint4*)(stage + off) = *src;
        }
    };

    load_stage(0, kbase);
    __syncthreads();

    int lrow = lane & 15;
    int lkh  = lane >> 4;

    for (int ch = 0; ch < 126; ch++) {
        int s = ch & 1;
        if (ch + 1 < 126) load_stage(s ^ 1, kbase + (ch + 1) * 32);

        uint32_t st = sb + s * ST_BYTES;
        #pragma unroll
        for (int ks = 0; ks < 2; ks++) {
            uint32_t kofs = ks * 32 + lkh * 16;

            uint32_t ah[2][4], al[2][4];
            #pragma unroll
            for (int mf = 0; mf < 2; mf++) {
                uint32_t rowb = (wr * 32 + mf * 16 + lrow) * KPAD_B + kofs;
                ldsm_x4(ah[mf], st + OFF_AH + rowb);
                ldsm_x4(al[mf], st + OFF_AL + rowb);
            }
            uint32_t bh[2][4], bl[2][4];
            #pragma unroll
            for (int pr = 0; pr < 2; pr++) {
                uint32_t rowb = (wc * 32 + pr * 16 + lrow) * KPAD_B + kofs;
                ldsm_x4(bh[pr], st + OFF_BH + rowb);
                ldsm_x4(bl[pr], st + OFF_BL + rowb);
            }

            #pragma unroll
            for (int mf = 0; mf < 2; mf++)
                #pragma unroll
                for (int nf = 0; nf < 4; nf++) {
                    int pr = nf >> 1, wch = nf & 1;
                    uint32_t bh0 = bh[pr][wch], bh1 = bh[pr][wch + 2];
                    uint32_t bl0 = bl[pr][wch], bl1 = bl[pr][wch + 2];
                    mma_bf16(acc[mf][nf], ah[mf], bh0, bh1);
                    mma_bf16(acc[mf][nf], ah[mf], bl0, bl1);
                    mma_bf16(acc[mf][nf], al[mf], bh0, bh1);
                }
        }
        __syncthreads();
    }

    // unscaled partials -> g_op[sk][b][c][n]
    int g  = lane >> 2;
    int cl = (lane & 3) * 2;
    #pragma unroll
    for (int mf = 0; mf < 2; mf++) {
        int nbase = n0 + wr * 32 + mf * 16 + g;
        #pragma unroll
        for (int nf = 0; nf < 4; nf++) {
            int c = wc * 32 + nf * 8 + cl;
            size_t o0 = (size_t)sk * BCN + ((size_t)b * Cn + c) * Nn;
            g_op[o0 + nbase]          = acc[mf][nf][0];
            g_op[o0 + Nn + nbase]     = acc[mf][nf][1];
            g_op[o0 + nbase + 8]      = acc[mf][nf][2];
            g_op[o0 + Nn + nbase + 8] = acc[mf][nf][3];
        }
    }
}

// ---------------------------------------------------------------------------
// Stage F: reduce 2 inv partials + 2/N scale
// ---------------------------------------------------------------------------
__global__ void __launch_bounds__(256) inv_reduce(float* __restrict__ out)
{
    const float sc = 2.0f / (float)Nn;
    size_t i = ((size_t)blockIdx.x * 256 + threadIdx.x) * 4;
    float4 a = *(const float4*)&g_op[i];
    float4 b = *(const float4*)&g_op[BCN + i];
    *(float4*)&out[i] = make_float4((a.x + b.x) * sc, (a.y + b.y) * sc,
                                    (a.z + b.z) * sc, (a.w + b.w) * sc);
}

// ---------------------------------------------------------------------------
extern "C" void kernel_launch(void* const* d_in, const int* in_sizes, int n_in,
                              void* d_out, int out_size)
{
    const float* x    = (const float*)d_in[0];
    const float* emb  = (const float*)d_in[1];
    const float* Vfr  = (const float*)d_in[2];
    const float* Vfi  = (const float*)d_in[3];
    const float* Vir  = (const float*)d_in[4];
    const float* Vii  = (const float*)d_in[5];
    const float* w1r  = (const float*)d_in[6];
    const float* w1i  = (const float*)d_in[7];
    const float* w2r  = (const float*)d_in[8];
    const float* w2i  = (const float*)d_in[9];
    const float* m1r  = (const float*)d_in[10];
    const float* m1i  = (const float*)d_in[11];
    const float* m2r  = (const float*)d_in[12];
    const float* m2i  = (const float*)d_in[13];
    float* out = (float*)d_out;

    cudaFuncSetAttribute(fwd_mma_warp, cudaFuncAttributeMaxDynamicSharedMemorySize, SMEM_DYN);
    cudaFuncSetAttribute(inv_mma_warp, cudaFuncAttributeMaxDynamicSharedMemorySize, SMEM_DYN);

    phi_kernel  <<<dim3(64, 8), 256>>>(emb, m1r, m1i, m2r, m2i);
    x_convert   <<<dim3(512), 256>>>(x);                 // 1,048,576 / 2048
    vf_convert  <<<dim3(4096), 256>>>(Vfr, Vfi);         // 8,388,608 / 2048
    vi_convert  <<<dim3(8064), 256>>>(Vir, Vii);         // 16,515,072 / 2048
    fwd_mma_warp<<<dim3(32, 8), 256, SMEM_DYN>>>();
    mode_mix    <<<dim3(64, 2), 256>>>(w1r, w1i, w2r, w2i);
    inv_mma_warp<<<dim3(16, 8, 2), 256, SMEM_DYN>>>();
    inv_reduce  <<<dim3(1024), 256>>>(out);
}